// round 15
// baseline (speedup 1.0000x reference)
#include <cuda_runtime.h>
#include <cuda_fp16.h>
#include <cstdint>
#include <math.h>

// ---------------------------------------------------------------------------
// PFMLPScaledXY via fp16 mma.sync.m16n8k16 (ptxas target = plain sm_100).
//   Lk(inp) = p0*(inp@Wk0) + p1*(inp@Wk1) + p0*bk0 + p1*bk1
// R15 = R14 resubmit (R14 hit a container-infra failure; no data).
// Hypothesis under test: ldmatrix.trans (all B fragments) is half-rate.
// Weights pre-transposed to [mode][N][K] once in preproc; B smem tiles are
// n-major so B fragments come from NON-trans ldsm_x4 (thread t -> row t/4,
// elems (t%4)*2 == the m16n8k16 B fragment layout). Same instruction counts,
// same conflict-free swizzle; only .trans removed from the hot loop.
// ---------------------------------------------------------------------------

#define NTHREADS 256
#define TBM 128
#define TBN 64      // per mode
#define TBK 64

// scratch (__device__ globals: allocation-free rule)
__device__ __half g_xh  [32768ull * 256];
__device__ __half g_w1t [2ull * 1024 * 256];    // [mode][N=1024][K=256]
__device__ __half g_w2t [2ull * 1024 * 1024];   // [mode][N=1024][K=1024]
__device__ __half g_w3t [2ull * 64 * 1024];     // [mode][N=64][K=1024]
__device__ __half g_h1  [32768ull * 1024];
__device__ __half g_h2  [32768ull * 1024];

// ---------------- PTX helpers ----------------------------------------------
__device__ __forceinline__ uint32_t smem_u32(const void* p) {
    return (uint32_t)__cvta_generic_to_shared(p);
}
__device__ __forceinline__ void cp_async16(uint32_t s, const void* g) {
    asm volatile("cp.async.cg.shared.global [%0], [%1], 16;" :: "r"(s), "l"(g));
}
__device__ __forceinline__ void cp_commit() {
    asm volatile("cp.async.commit_group;");
}
template <int N> __device__ __forceinline__ void cp_wait() {
    asm volatile("cp.async.wait_group %0;" :: "n"(N));
}
__device__ __forceinline__ void ldsm_x4(uint32_t* r, uint32_t a) {
    asm volatile("ldmatrix.sync.aligned.m8n8.x4.shared.b16 {%0,%1,%2,%3}, [%4];"
                 : "=r"(r[0]), "=r"(r[1]), "=r"(r[2]), "=r"(r[3]) : "r"(a));
}
__device__ __forceinline__ void mma_f16(float* d, const uint32_t* a,
                                        uint32_t b0, uint32_t b1) {
    asm volatile(
        "mma.sync.aligned.m16n8k16.row.col.f32.f16.f16.f32 "
        "{%0,%1,%2,%3}, {%4,%5,%6,%7}, {%8,%9}, {%0,%1,%2,%3};"
        : "+f"(d[0]), "+f"(d[1]), "+f"(d[2]), "+f"(d[3])
        : "r"(a[0]), "r"(a[1]), "r"(a[2]), "r"(a[3]), "r"(b0), "r"(b1));
}
__device__ __forceinline__ float elu_fast(float v) {
    return v > 0.0f ? v : (__expf(v) - 1.0f);
}
__device__ __forceinline__ uint32_t h2_bits(__half2 h) {
    __half2_raw r = *reinterpret_cast<__half2_raw*>(&h);
    return (uint32_t)r.x | ((uint32_t)r.y << 16);
}

// ---------------- preprocessing --------------------------------------------
// x [M,258] f32 -> xh [M,256] half (x rows only 8B-aligned: stride 1032B)
__global__ void conv_x_kernel(const float* __restrict__ x, __half* __restrict__ xh) {
    int idx = blockIdx.x * blockDim.x + threadIdx.x;   // M*32, 8 cols/thread
    size_t r = (size_t)idx >> 5;
    int c = (idx & 31) * 8;
    const float* src = x + r * 258 + c;
    float2 v0 = *reinterpret_cast<const float2*>(src);
    float2 v1 = *reinterpret_cast<const float2*>(src + 2);
    float2 v2 = *reinterpret_cast<const float2*>(src + 4);
    float2 v3 = *reinterpret_cast<const float2*>(src + 6);
    uint4 o;
    o.x = h2_bits(__floats2half2_rn(v0.x, v0.y));
    o.y = h2_bits(__floats2half2_rn(v1.x, v1.y));
    o.z = h2_bits(__floats2half2_rn(v2.x, v2.y));
    o.w = h2_bits(__floats2half2_rn(v3.x, v3.y));
    *reinterpret_cast<uint4*>(xh + r * 256 + c) = o;
}

// w [2,K,N] f32 -> wt [2,N,K] half, 32x32 smem transpose tiles
__global__ void transpose_conv_kernel(const float* __restrict__ w,
                                      __half* __restrict__ wt, int K, int N) {
    __shared__ float t[32][33];
    int n0 = blockIdx.x * 32, k0 = blockIdx.y * 32, mode = blockIdx.z;
    int tx = threadIdx.x, ty = threadIdx.y;
    const float* wm = w + (size_t)mode * K * N;
    __half* wtm = wt + (size_t)mode * N * K;
    #pragma unroll
    for (int i = 0; i < 32; i += 8)
        t[ty + i][tx] = wm[(size_t)(k0 + ty + i) * N + n0 + tx];
    __syncthreads();
    #pragma unroll
    for (int i = 0; i < 32; i += 8)
        wtm[(size_t)(n0 + ty + i) * K + k0 + tx] = __float2half_rn(t[tx][ty + i]);
}

// ---------------- main GEMM ------------------------------------------------
// A  [Mtot,K] half row-major (lda == K).
// Bt [2][Nld][K] half: TRANSPOSED weights, n-major.
// Per CTA: rows blockM..+128, cols blockN..+64 (both modes).
// SMEM tiles: 128-byte rows (64 halves); 16B chunk j of row q stored at chunk
// (j ^ (q&7)) -> conflict-free for cp.async writes AND ldmatrix reads.
// A-tile rows = m (k-major); B-tile rows = n (k-major) -> NON-trans ldsm.
template <int K, bool DO_ELU, bool OUT_HALF>
__global__ void __launch_bounds__(NTHREADS, 2) hgemm(
    const __half* __restrict__ A,
    const __half* __restrict__ Bt, int Nld,
    const float* __restrict__ bias0, const float* __restrict__ bias1,
    const float* __restrict__ xphase,
    void* __restrict__ Cv, int ldc)
{
    constexpr int A_BYTES = TBM * 128;              // 16384
    constexpr int B_BYTES = TBN * 128;              // 8192 per mode (64 n-rows)
    constexpr int STAGE   = A_BYTES + 2 * B_BYTES;  // 32768
    constexpr int NK      = K / TBK;

    extern __shared__ char smem[];
    const uint32_t sm = smem_u32(smem);

    const int tid  = threadIdx.x;
    const int wid  = tid >> 5;
    const int lane = tid & 31;
    const int warp_m = wid & 3;      // 4 warps over M (32 rows)
    const int warp_n = wid >> 2;     // 2 warps over N (32 cols)
    const size_t blockM = (size_t)blockIdx.y * TBM;
    const int blockN = blockIdx.x * TBN;

    float acc[2][2][4][4];           // [mode][mtile][ntile][frag]
    #pragma unroll
    for (int m = 0; m < 2; m++)
        #pragma unroll
        for (int i = 0; i < 2; i++)
            #pragma unroll
            for (int j = 0; j < 4; j++)
                #pragma unroll
                for (int q = 0; q < 4; q++) acc[m][i][j][q] = 0.0f;

    auto load_stage = [&](int kt, int buf) {
        const int k0 = kt * TBK;
        const uint32_t st = sm + buf * STAGE;
        // A: 128 m-rows x 8 chunks = 1024 chunks, 4/thread
        #pragma unroll
        for (int c = 0; c < 4; c++) {
            int p = c * NTHREADS + tid;
            int row = p >> 3, j = p & 7;
            uint32_t dst = st + row * 128 + ((j ^ (row & 7)) << 4);
            cp_async16(dst, A + (blockM + row) * (size_t)K + k0 + j * 8);
        }
        // B: per mode 64 n-rows x 8 chunks = 512 chunks, 2/thread
        #pragma unroll
        for (int m = 0; m < 2; m++) {
            const __half* Bm = Bt + ((size_t)m * Nld + blockN) * K;
            const uint32_t bst = st + A_BYTES + m * B_BYTES;
            #pragma unroll
            for (int c = 0; c < 2; c++) {
                int p = c * NTHREADS + tid;
                int row = p >> 3, j = p & 7;
                uint32_t dst = bst + row * 128 + ((j ^ (row & 7)) << 4);
                cp_async16(dst, Bm + (size_t)row * K + k0 + j * 8);
            }
        }
        cp_commit();
    };

    auto consume_stage = [&](int i) {
        const uint32_t st = sm + (i % 3) * STAGE;
        #pragma unroll
        for (int kk = 0; kk < 4; kk++) {
            // A fragments (non-trans): lanes 0-15 rows, 16-31 second k-octet
            uint32_t a[2][4];
            const int jA = kk * 2 + (lane >> 4);
            #pragma unroll
            for (int mt = 0; mt < 2; mt++) {
                const int m = warp_m * 32 + mt * 16 + (lane & 15);
                ldsm_x4(a[mt], st + m * 128 + ((jA ^ (m & 7)) << 4));
            }
            // B fragments (non-trans on n-major tile):
            //   matrix idx = lane>>3: bit1 = n-octet, bit0 = k-octet
            const int n_oct = (lane >> 4) & 1;
            const int k_oct = (lane >> 3) & 1;
            const int jB = kk * 2 + k_oct;
            #pragma unroll
            for (int m = 0; m < 2; m++) {
                const uint32_t bst = st + A_BYTES + m * B_BYTES;
                #pragma unroll
                for (int ntg = 0; ntg < 2; ntg++) {
                    const int nrow = warp_n * 32 + ntg * 16 + n_oct * 8 + (lane & 7);
                    uint32_t b[4];   // b0=(noct0,klo) b1=(noct0,khi) b2=(noct1,klo) b3=(noct1,khi)
                    ldsm_x4(b, bst + nrow * 128 + ((jB ^ (nrow & 7)) << 4));
                    mma_f16(acc[m][0][ntg * 2 + 0], a[0], b[0], b[1]);
                    mma_f16(acc[m][0][ntg * 2 + 1], a[0], b[2], b[3]);
                    mma_f16(acc[m][1][ntg * 2 + 0], a[1], b[0], b[1]);
                    mma_f16(acc[m][1][ntg * 2 + 1], a[1], b[2], b[3]);
                }
            }
        }
    };

    // 3-stage circular pipeline, loads 2 ahead, ONE barrier per iteration.
    load_stage(0, 0);
    load_stage(1, 1);

    #pragma unroll
    for (int i = 0; i < NK - 1; i++) {
        cp_wait<1>();
        __syncthreads();                       // all warps done with buf (i-1)%3
        if (i + 2 < NK) load_stage(i + 2, (i + 2) % 3);
        consume_stage(i);
    }
    cp_wait<0>();
    __syncthreads();
    consume_stage(NK - 1);

    // ---- epilogue: phase mix + bias + ELU ----------------------------------
    #pragma unroll
    for (int mt = 0; mt < 2; mt++) {
        #pragma unroll
        for (int rr = 0; rr < 2; rr++) {
            const size_t r = blockM + warp_m * 32 + mt * 16 + rr * 8 + (lane >> 2);
            const float2 ph = *reinterpret_cast<const float2*>(xphase + r * 258 + 256);
            const float p0 = ph.x, p1 = ph.y;
            #pragma unroll
            for (int nt = 0; nt < 4; nt++) {
                const int col = blockN + warp_n * 32 + nt * 8 + (lane & 3) * 2;
                float v0 = p0 * acc[0][mt][nt][rr * 2 + 0]
                         + p1 * acc[1][mt][nt][rr * 2 + 0]
                         + p0 * __ldg(bias0 + col) + p1 * __ldg(bias1 + col);
                float v1 = p0 * acc[0][mt][nt][rr * 2 + 1]
                         + p1 * acc[1][mt][nt][rr * 2 + 1]
                         + p0 * __ldg(bias0 + col + 1) + p1 * __ldg(bias1 + col + 1);
                if (DO_ELU) {
                    v0 = elu_fast(v0);
                    v1 = elu_fast(v1);
                }
                if (OUT_HALF) {
                    __half* C = (__half*)Cv;
                    *reinterpret_cast<__half2*>(C + r * ldc + col) =
                        __floats2half2_rn(v0, v1);
                } else {
                    float* C = (float*)Cv;
                    *reinterpret_cast<float2*>(C + r * ldc + col) =
                        make_float2(v0, v1);
                }
            }
        }
    }
}

// ---------------------------------------------------------------------------
extern "C" void kernel_launch(void* const* d_in, const int* in_sizes, int n_in,
                              void* d_out, int out_size)
{
    const float* x  = (const float*)d_in[0];
    const float* w1 = (const float*)d_in[1];
    const float* b1 = (const float*)d_in[2];
    const float* w2 = (const float*)d_in[3];
    const float* b2 = (const float*)d_in[4];
    const float* w3 = (const float*)d_in[5];
    const float* b3 = (const float*)d_in[6];
    float* out = (float*)d_out;

    const int M = 32768, DIN = 256, H = 1024, DOUT = 64;

    __half *xh, *w1t, *w2t, *w3t, *h1, *h2;
    cudaGetSymbolAddress((void**)&xh,  g_xh);
    cudaGetSymbolAddress((void**)&w1t, g_w1t);
    cudaGetSymbolAddress((void**)&w2t, g_w2t);
    cudaGetSymbolAddress((void**)&w3t, g_w3t);
    cudaGetSymbolAddress((void**)&h1,  g_h1);
    cudaGetSymbolAddress((void**)&h2,  g_h2);

    const int SMEM = 3 * (128 * 128 + 2 * 64 * 128);   // 98304 (3 stages)
    cudaFuncSetAttribute((const void*)hgemm<256, true, true>,
                         cudaFuncAttributeMaxDynamicSharedMemorySize, SMEM);
    cudaFuncSetAttribute((const void*)hgemm<1024, true, true>,
                         cudaFuncAttributeMaxDynamicSharedMemorySize, SMEM);
    cudaFuncSetAttribute((const void*)hgemm<1024, false, false>,
                         cudaFuncAttributeMaxDynamicSharedMemorySize, SMEM);

    // preprocessing: x convert + weight transpose/convert
    conv_x_kernel<<<M * 32 / 256, 256>>>(x, xh);
    {
        dim3 b(32, 8);
        transpose_conv_kernel<<<dim3(H / 32,    DIN / 32, 2), b>>>(w1, w1t, DIN, H);
        transpose_conv_kernel<<<dim3(H / 32,    H   / 32, 2), b>>>(w2, w2t, H, H);
        transpose_conv_kernel<<<dim3(DOUT / 32, H   / 32, 2), b>>>(w3, w3t, H, DOUT);
    }

    dim3 blk(NTHREADS);
    // L1: xh @ w1^T -> elu -> h1 (half)
    hgemm<256, true, true><<<dim3(H / TBN, M / TBM), blk, SMEM>>>(
        xh, w1t, H, b1, b1 + H, x, h1, H);
    // L2: h1 @ w2^T -> elu -> h2 (half)
    hgemm<1024, true, true><<<dim3(H / TBN, M / TBM), blk, SMEM>>>(
        h1, w2t, H, b2, b2 + H, x, h2, H);
    // L3: h2 @ w3^T -> out (f32)
    hgemm<1024, false, false><<<dim3(DOUT / TBN, M / TBM), blk, SMEM>>>(
        h2, w3t, DOUT, b3, b3 + DOUT, x, out, DOUT);
}

// round 16
// speedup vs baseline: 1.0084x; 1.0084x over previous
#include <cuda_runtime.h>
#include <cuda_fp16.h>
#include <cstdint>
#include <math.h>

// ---------------------------------------------------------------------------
// PFMLPScaledXY via fp16 mma.sync.m16n8k16 (ptxas target = plain sm_100).
//   Lk(inp) = p0*(inp@Wk0) + p1*(inp@Wk1) + p0*bk0 + p1*bk1
// R16 = R13 verbatim (best measured: 456.2us). R15 falsified the
// ldmatrix.trans half-rate hypothesis (neutral mainloop, +2.5us preproc), so
// the converged design is final: fused preproc, 3-stage/1-barrier cp.async
// pipeline, 32x32x2mode warp tiles @ 2 CTAs/SM, fast ELU, peeled tail,
// reverse-M L3.
// ---------------------------------------------------------------------------

#define NTHREADS 256
#define TBM 128
#define TBN 64      // per mode
#define TBK 64

// scratch (__device__ globals: allocation-free rule)
__device__ __half g_xh [32768ull * 256];
__device__ __half g_w1h[2ull * 256 * 1024];
__device__ __half g_w2h[2ull * 1024 * 1024];
__device__ __half g_w3h[2ull * 1024 * 64];
__device__ __half g_h1 [32768ull * 1024];
__device__ __half g_h2 [32768ull * 1024];

// ---------------- PTX helpers ----------------------------------------------
__device__ __forceinline__ uint32_t smem_u32(const void* p) {
    return (uint32_t)__cvta_generic_to_shared(p);
}
__device__ __forceinline__ void cp_async16(uint32_t s, const void* g) {
    asm volatile("cp.async.cg.shared.global [%0], [%1], 16;" :: "r"(s), "l"(g));
}
__device__ __forceinline__ void cp_commit() {
    asm volatile("cp.async.commit_group;");
}
template <int N> __device__ __forceinline__ void cp_wait() {
    asm volatile("cp.async.wait_group %0;" :: "n"(N));
}
__device__ __forceinline__ void ldsm_x4(uint32_t* r, uint32_t a) {
    asm volatile("ldmatrix.sync.aligned.m8n8.x4.shared.b16 {%0,%1,%2,%3}, [%4];"
                 : "=r"(r[0]), "=r"(r[1]), "=r"(r[2]), "=r"(r[3]) : "r"(a));
}
__device__ __forceinline__ void ldsm_x4_t(uint32_t* r, uint32_t a) {
    asm volatile("ldmatrix.sync.aligned.m8n8.x4.trans.shared.b16 {%0,%1,%2,%3}, [%4];"
                 : "=r"(r[0]), "=r"(r[1]), "=r"(r[2]), "=r"(r[3]) : "r"(a));
}
__device__ __forceinline__ void mma_f16(float* d, const uint32_t* a,
                                        uint32_t b0, uint32_t b1) {
    asm volatile(
        "mma.sync.aligned.m16n8k16.row.col.f32.f16.f16.f32 "
        "{%0,%1,%2,%3}, {%4,%5,%6,%7}, {%8,%9}, {%0,%1,%2,%3};"
        : "+f"(d[0]), "+f"(d[1]), "+f"(d[2]), "+f"(d[3])
        : "r"(a[0]), "r"(a[1]), "r"(a[2]), "r"(a[3]), "r"(b0), "r"(b1));
}
__device__ __forceinline__ float elu_fast(float v) {
    return v > 0.0f ? v : (__expf(v) - 1.0f);
}
__device__ __forceinline__ uint32_t h2_bits(__half2 h) {
    __half2_raw r = *reinterpret_cast<__half2_raw*>(&h);
    return (uint32_t)r.x | ((uint32_t)r.y << 16);
}

// ---------------- fused preprocessing --------------------------------------
__global__ void conv_all_kernel(const float* __restrict__ x, __half* __restrict__ xh,
                                const float* __restrict__ w1, __half* __restrict__ w1h,
                                const float* __restrict__ w2, __half* __restrict__ w2h,
                                const float* __restrict__ w3, __half* __restrict__ w3h,
                                int nx, int n1, int n2, int n3) {
    int idx = blockIdx.x * blockDim.x + threadIdx.x;
    if (idx < nx) {
        // x path: 8 columns per thread (x rows only 8B-aligned: stride 1032B)
        size_t r = (size_t)idx >> 5;
        int c = (idx & 31) * 8;
        const float* src = x + r * 258 + c;
        float2 v0 = *reinterpret_cast<const float2*>(src);
        float2 v1 = *reinterpret_cast<const float2*>(src + 2);
        float2 v2 = *reinterpret_cast<const float2*>(src + 4);
        float2 v3 = *reinterpret_cast<const float2*>(src + 6);
        uint4 o;
        o.x = h2_bits(__floats2half2_rn(v0.x, v0.y));
        o.y = h2_bits(__floats2half2_rn(v1.x, v1.y));
        o.z = h2_bits(__floats2half2_rn(v2.x, v2.y));
        o.w = h2_bits(__floats2half2_rn(v3.x, v3.y));
        *reinterpret_cast<uint4*>(xh + r * 256 + c) = o;
        return;
    }
    int wi = idx - nx;
    const float* src; __half* dst; int i;
    if (wi < n1)                { src = w1; dst = w1h; i = wi; }
    else if (wi < n1 + n2)      { src = w2; dst = w2h; i = wi - n1; }
    else if (wi < n1 + n2 + n3) { src = w3; dst = w3h; i = wi - n1 - n2; }
    else return;
    float4 v = reinterpret_cast<const float4*>(src)[i];
    reinterpret_cast<__half2*>(dst)[i * 2]     = __floats2half2_rn(v.x, v.y);
    reinterpret_cast<__half2*>(dst)[i * 2 + 1] = __floats2half2_rn(v.z, v.w);
}

// ---------------- main GEMM ------------------------------------------------
// A [Mtot,K] half row-major (lda == K), B [2][K,ldb] half row-major.
// Per CTA: rows blockM..+128, cols blockN..+64 (both modes).
// SMEM tile: 128-byte rows (64 halves); 16B chunk j of row m stored at chunk
// (j ^ (m&7)) -> conflict-free for cp.async writes AND ldmatrix reads.
// REVM: traverse M-tiles in descending order.
template <int K, bool DO_ELU, bool OUT_HALF, bool REVM>
__global__ void __launch_bounds__(NTHREADS, 2) hgemm(
    const __half* __restrict__ A,
    const __half* __restrict__ B, size_t modeStride, int ldb,
    const float* __restrict__ bias0, const float* __restrict__ bias1,
    const float* __restrict__ xphase,
    void* __restrict__ Cv, int ldc)
{
    constexpr int A_BYTES = TBM * 128;              // 16384
    constexpr int B_BYTES = TBK * 128;              // 8192 per mode
    constexpr int STAGE   = A_BYTES + 2 * B_BYTES;  // 32768
    constexpr int NK      = K / TBK;

    extern __shared__ char smem[];
    const uint32_t sm = smem_u32(smem);

    const int tid  = threadIdx.x;
    const int wid  = tid >> 5;
    const int lane = tid & 31;
    const int warp_m = wid & 3;      // 4 warps over M (32 rows)
    const int warp_n = wid >> 2;     // 2 warps over N (32 cols)
    const unsigned by = REVM ? (gridDim.y - 1 - blockIdx.y) : blockIdx.y;
    const size_t blockM = (size_t)by * TBM;
    const int blockN = blockIdx.x * TBN;

    float acc[2][2][4][4];           // [mode][mtile][ntile][frag]
    #pragma unroll
    for (int m = 0; m < 2; m++)
        #pragma unroll
        for (int i = 0; i < 2; i++)
            #pragma unroll
            for (int j = 0; j < 4; j++)
                #pragma unroll
                for (int q = 0; q < 4; q++) acc[m][i][j][q] = 0.0f;

    auto load_stage = [&](int kt, int buf) {
        const int k0 = kt * TBK;
        const uint32_t st = sm + buf * STAGE;
        // A: 128 rows x 8 chunks = 1024 chunks, 4/thread
        #pragma unroll
        for (int c = 0; c < 4; c++) {
            int p = c * NTHREADS + tid;
            int row = p >> 3, j = p & 7;
            uint32_t dst = st + row * 128 + ((j ^ (row & 7)) << 4);
            cp_async16(dst, A + (blockM + row) * (size_t)K + k0 + j * 8);
        }
        // B: per mode 64 rows x 8 chunks = 512 chunks, 2/thread
        #pragma unroll
        for (int m = 0; m < 2; m++) {
            const __half* Bm = B + m * modeStride;
            const uint32_t bst = st + A_BYTES + m * B_BYTES;
            #pragma unroll
            for (int c = 0; c < 2; c++) {
                int p = c * NTHREADS + tid;
                int row = p >> 3, j = p & 7;
                uint32_t dst = bst + row * 128 + ((j ^ (row & 7)) << 4);
                cp_async16(dst, Bm + (size_t)(k0 + row) * ldb + blockN + j * 8);
            }
        }
        cp_commit();
    };

    auto consume_stage = [&](int i) {
        const uint32_t st = sm + (i % 3) * STAGE;
        #pragma unroll
        for (int kk = 0; kk < 4; kk++) {
            uint32_t a[2][4];
            const int jA = kk * 2 + (lane >> 4);
            #pragma unroll
            for (int mt = 0; mt < 2; mt++) {
                const int m = warp_m * 32 + mt * 16 + (lane & 15);
                ldsm_x4(a[mt], st + m * 128 + ((jA ^ (m & 7)) << 4));
            }
            const int krow = kk * 16 + (lane & 15);
            #pragma unroll
            for (int m = 0; m < 2; m++) {
                const uint32_t bst = st + A_BYTES + m * B_BYTES;
                #pragma unroll
                for (int ntg = 0; ntg < 2; ntg++) {
                    const int jn = warp_n * 4 + ntg * 2 + (lane >> 4);
                    uint32_t b[4];
                    ldsm_x4_t(b, bst + krow * 128 + ((jn ^ (krow & 7)) << 4));
                    mma_f16(acc[m][0][ntg * 2 + 0], a[0], b[0], b[1]);
                    mma_f16(acc[m][0][ntg * 2 + 1], a[0], b[2], b[3]);
                    mma_f16(acc[m][1][ntg * 2 + 0], a[1], b[0], b[1]);
                    mma_f16(acc[m][1][ntg * 2 + 1], a[1], b[2], b[3]);
                }
            }
        }
    };

    // 3-stage circular pipeline, loads 2 ahead, ONE barrier per iteration.
    load_stage(0, 0);
    load_stage(1, 1);

    #pragma unroll
    for (int i = 0; i < NK - 1; i++) {
        cp_wait<1>();
        __syncthreads();                       // all warps done with buf (i-1)%3
        if (i + 2 < NK) load_stage(i + 2, (i + 2) % 3);
        consume_stage(i);
    }
    // peeled final iteration (no further loads, drain all)
    cp_wait<0>();
    __syncthreads();
    consume_stage(NK - 1);

    // ---- epilogue: phase mix + bias + ELU ----------------------------------
    #pragma unroll
    for (int mt = 0; mt < 2; mt++) {
        #pragma unroll
        for (int rr = 0; rr < 2; rr++) {
            const size_t r = blockM + warp_m * 32 + mt * 16 + rr * 8 + (lane >> 2);
            const float2 ph = *reinterpret_cast<const float2*>(xphase + r * 258 + 256);
            const float p0 = ph.x, p1 = ph.y;
            #pragma unroll
            for (int nt = 0; nt < 4; nt++) {
                const int col = blockN + warp_n * 32 + nt * 8 + (lane & 3) * 2;
                float v0 = p0 * acc[0][mt][nt][rr * 2 + 0]
                         + p1 * acc[1][mt][nt][rr * 2 + 0]
                         + p0 * __ldg(bias0 + col) + p1 * __ldg(bias1 + col);
                float v1 = p0 * acc[0][mt][nt][rr * 2 + 1]
                         + p1 * acc[1][mt][nt][rr * 2 + 1]
                         + p0 * __ldg(bias0 + col + 1) + p1 * __ldg(bias1 + col + 1);
                if (DO_ELU) {
                    v0 = elu_fast(v0);
                    v1 = elu_fast(v1);
                }
                if (OUT_HALF) {
                    __half* C = (__half*)Cv;
                    *reinterpret_cast<__half2*>(C + r * ldc + col) =
                        __floats2half2_rn(v0, v1);
                } else {
                    float* C = (float*)Cv;
                    *reinterpret_cast<float2*>(C + r * ldc + col) =
                        make_float2(v0, v1);
                }
            }
        }
    }
}

// ---------------------------------------------------------------------------
extern "C" void kernel_launch(void* const* d_in, const int* in_sizes, int n_in,
                              void* d_out, int out_size)
{
    const float* x  = (const float*)d_in[0];
    const float* w1 = (const float*)d_in[1];
    const float* b1 = (const float*)d_in[2];
    const float* w2 = (const float*)d_in[3];
    const float* b2 = (const float*)d_in[4];
    const float* w3 = (const float*)d_in[5];
    const float* b3 = (const float*)d_in[6];
    float* out = (float*)d_out;

    const int M = 32768, DIN = 256, H = 1024, DOUT = 64;

    __half *xh, *w1h, *w2h, *w3h, *h1, *h2;
    cudaGetSymbolAddress((void**)&xh,  g_xh);
    cudaGetSymbolAddress((void**)&w1h, g_w1h);
    cudaGetSymbolAddress((void**)&w2h, g_w2h);
    cudaGetSymbolAddress((void**)&w3h, g_w3h);
    cudaGetSymbolAddress((void**)&h1,  g_h1);
    cudaGetSymbolAddress((void**)&h2,  g_h2);

    const int SMEM = 3 * (128 * 128 + 2 * 64 * 128);   // 98304 (3 stages)
    cudaFuncSetAttribute((const void*)hgemm<256, true, true, false>,
                         cudaFuncAttributeMaxDynamicSharedMemorySize, SMEM);
    cudaFuncSetAttribute((const void*)hgemm<1024, true, true, false>,
                         cudaFuncAttributeMaxDynamicSharedMemorySize, SMEM);
    cudaFuncSetAttribute((const void*)hgemm<1024, false, false, true>,
                         cudaFuncAttributeMaxDynamicSharedMemorySize, SMEM);

    // fused preprocessing: one launch for x + all weights
    {
        int nx = M * DIN / 8;                          // 1048576 (8 cols/thread)
        int n1 = 2 * DIN * H / 4, n2 = 2 * H * H / 4, n3 = 2 * H * DOUT / 4;
        int total = nx + n1 + n2 + n3;
        conv_all_kernel<<<(total + 255) / 256, 256>>>(
            x, xh, w1, w1h, w2, w2h, w3, w3h, nx, n1, n2, n3);
    }

    dim3 blk(NTHREADS);
    // L1: xh @ w1 -> elu -> h1 (half)
    hgemm<256, true, true, false><<<dim3(H / TBN, M / TBM), blk, SMEM>>>(
        xh, w1h, (size_t)DIN * H, H, b1, b1 + H, x, h1, H);
    // L2: h1 @ w2 -> elu -> h2 (half)
    hgemm<1024, true, true, false><<<dim3(H / TBN, M / TBM), blk, SMEM>>>(
        h1, w2h, (size_t)H * H, H, b2, b2 + H, x, h2, H);
    // L3: h2 @ w3 -> out (f32), reverse M order
    hgemm<1024, false, false, true><<<dim3(DOUT / TBN, M / TBM), blk, SMEM>>>(
        h2, w3h, (size_t)H * DOUT, DOUT, b3, b3 + DOUT, x, out, DOUT);
}